// round 14
// baseline (speedup 1.0000x reference)
#include <cuda_runtime.h>
#include <cuda_fp16.h>
#include <math.h>
#include <stdint.h>

// Problem constants
#define BB   4
#define TT   2048
#define CC   2048
#define HH   16
#define DH   128
#define BT   (BB * TT)          // 8192
#define ELEMS ((size_t)BT * CC) // 16777216

#define RMS_EPS 1.1920928955078125e-07f
#define WSCALE     32.0f        // weight pre-scale (keeps small weights normal in fp16)
#define WSCALE_INV 0.03125f

// ---------------- scratch (device globals; no allocation allowed) ----------
__device__ __align__(16) float g_q[ELEMS];
__device__ __align__(16) float g_k[ELEMS];
__device__ __align__(16) __half g_xh[ELEMS];
__device__ __align__(16) __half g_yh[ELEMS];
__device__ __align__(16) __half g_qh[ELEMS];
__device__ __align__(16) __half g_kh[ELEMS];
__device__ __align__(16) __half g_vh[ELEMS];
__device__ __align__(16) __half g_wh[4][(size_t)CC * CC];
__device__ __align__(16) float g_cos[TT * 64];
__device__ __align__(16) float g_sin[TT * 64];

// ======================= PTX helpers (portable, no 'a' features) ============
__device__ __forceinline__ uint32_t smem_u32(const void* p) {
    uint32_t a;
    asm("{ .reg .u64 t; cvta.to.shared.u64 t, %1; cvt.u32.u64 %0, t; }"
        : "=r"(a) : "l"(p));
    return a;
}

__device__ __forceinline__ void ldsm_x4(uint32_t* r, uint32_t addr) {
    asm volatile("ldmatrix.sync.aligned.m8n8.x4.shared.b16 {%0,%1,%2,%3}, [%4];"
                 : "=r"(r[0]), "=r"(r[1]), "=r"(r[2]), "=r"(r[3]) : "r"(addr));
}
__device__ __forceinline__ void ldsm_x4_t(uint32_t* r, uint32_t addr) {
    asm volatile("ldmatrix.sync.aligned.m8n8.x4.trans.shared.b16 {%0,%1,%2,%3}, [%4];"
                 : "=r"(r[0]), "=r"(r[1]), "=r"(r[2]), "=r"(r[3]) : "r"(addr));
}

// fp16 MMA, fp32 accumulate
__device__ __forceinline__ void mma16816(float* d, const uint32_t* a,
                                         const uint32_t* b, const float* c) {
    asm volatile(
        "mma.sync.aligned.m16n8k16.row.col.f32.f16.f16.f32 "
        "{%0,%1,%2,%3}, {%4,%5,%6,%7}, {%8,%9}, {%10,%11,%12,%13};\n"
        : "=f"(d[0]), "=f"(d[1]), "=f"(d[2]), "=f"(d[3])
        : "r"(a[0]), "r"(a[1]), "r"(a[2]), "r"(a[3]),
          "r"(b[0]), "r"(b[1]),
          "f"(c[0]), "f"(c[1]), "f"(c[2]), "f"(c[3]));
}

#define CP_ASYNC16(sdst, gsrc) \
    asm volatile("cp.async.cg.shared.global [%0], [%1], 16;" \
                 :: "r"(sdst), "l"(gsrc) : "memory")
#define CP_COMMIT() asm volatile("cp.async.commit_group;" ::: "memory")
#define CP_WAIT1()  asm volatile("cp.async.wait_group 1;" ::: "memory")
#define CP_WAIT0()  asm volatile("cp.async.wait_group 0;" ::: "memory")

// pack two fp32 into f16x2 (first arg -> low half)
__device__ __forceinline__ uint32_t packh(float lo, float hi) {
    uint32_t d;
    asm("cvt.rn.f16x2.f32 %0, %1, %2;" : "=r"(d) : "f"(hi), "f"(lo));
    return d;
}

// fast e^x for x <= 0 (no MUFU): 2^y with rint + deg-5 poly, rel err ~2.4e-6
__device__ __forceinline__ float fexp(float x) {
    float y = x * 1.4426950408889634f;
    y = fmaxf(y, -126.0f);
    float nf = rintf(y);
    float f = y - nf;
    float p = 1.3333558146e-3f;
    p = fmaf(p, f, 9.6181291076e-3f);
    p = fmaf(p, f, 5.5504108664e-2f);
    p = fmaf(p, f, 2.4022650696e-1f);
    p = fmaf(p, f, 6.9314718056e-1f);
    p = fmaf(p, f, 1.0f);
    return __int_as_float(__float_as_int(p) + (((int)nf) << 23));
}

// ---------------- kernel: cast all 4 weights fp32 -> fp16 (x WSCALE) --------
__global__ __launch_bounds__(256) void castw4_kernel(const float* __restrict__ w0,
                                                     const float* __restrict__ w1,
                                                     const float* __restrict__ w2,
                                                     const float* __restrict__ w3,
                                                     __half* __restrict__ hi) {
    int gb = blockIdx.x >> 12;              // 4096 blocks per weight
    const float* in = (gb == 0) ? w0 : (gb == 1) ? w1 : (gb == 2) ? w2 : w3;
    size_t i = (size_t)(blockIdx.x & 4095) * 256 + threadIdx.x;
    float4 v = reinterpret_cast<const float4*>(in)[i];
    uint2 u;
    u.x = packh(v.x * WSCALE, v.y * WSCALE);
    u.y = packh(v.z * WSCALE, v.w * WSCALE);
    *reinterpret_cast<uint2*>(hi + (size_t)gb * CC * CC + 4 * i) = u;
}

// ---------------- kernel 1: rmsnorm over C, output fp16 ---------------------
__global__ __launch_bounds__(256) void rmsnorm_in_kernel(const float* __restrict__ in,
                                                         __half* __restrict__ xh) {
    int row = blockIdx.x;
    const float4* ip = reinterpret_cast<const float4*>(in) + (size_t)row * 512;
    int t = threadIdx.x;
    float4 a = ip[t];
    float4 b = ip[t + 256];
    float ss = a.x*a.x + a.y*a.y + a.z*a.z + a.w*a.w
             + b.x*b.x + b.y*b.y + b.z*b.z + b.w*b.w;
    __shared__ float red[8];
    #pragma unroll
    for (int o = 16; o > 0; o >>= 1) ss += __shfl_xor_sync(0xffffffffu, ss, o);
    if ((t & 31) == 0) red[t >> 5] = ss;
    __syncthreads();
    if (t < 8) {
        float v = red[t];
        #pragma unroll
        for (int o = 4; o > 0; o >>= 1) v += __shfl_xor_sync(0xffu, v, o);
        if (t == 0) red[0] = v;
    }
    __syncthreads();
    float sc = rsqrtf(red[0] * (1.0f / 2048.0f) + RMS_EPS);
    size_t base = (size_t)row * CC;
    uint2 u0, u1;
    u0.x = packh(a.x * sc, a.y * sc); u0.y = packh(a.z * sc, a.w * sc);
    u1.x = packh(b.x * sc, b.y * sc); u1.y = packh(b.z * sc, b.w * sc);
    *reinterpret_cast<uint2*>(xh + base + 4 * t)         = u0;
    *reinterpret_cast<uint2*>(xh + base + 4 * (t + 256)) = u1;
}

// ---------------- kernel 2: RoPE cos/sin tables -----------------------------
__global__ void rope_table_kernel() {
    int idx = blockIdx.x * blockDim.x + threadIdx.x;
    if (idx >= TT * 64) return;
    int t = idx >> 6;
    int p = idx & 63;
    double inv = pow(10000.0, -((double)p) / 64.0);
    float ang = (float)t * (float)inv;
    g_cos[idx] = cosf(ang);
    g_sin[idx] = sinf(ang);
}

// ---------------- kernel 3: 3-stage pipelined HMMA fp16 GEMM ----------------
// C[m,n] = (1/WSCALE) * sum_k Ah[m,k]*Wh[n,k]  (+ addend)
// Block 128x256, warp tile 64x64 (8 warps as 2x4), Kc=64, 3-stage cp.async.
#define QM 128
#define QN 256
#define QKC 64
#define LDT 72                      // smem row pitch halves (144B) -> conflict-free
#define A_ARR (QM * LDT * 2)        // 18432 bytes
#define W_ARR (QN * LDT * 2)        // 36864 bytes
#define BUF_B (A_ARR + W_ARR)       // 55296 bytes per stage
#define GEMM_SMEM (3 * BUF_B)       // 165888 bytes

__device__ __forceinline__ void gemm_chunk_load(
    uint32_t sbuf, const __half* __restrict__ Ah, const __half* __restrict__ Wh,
    int m0, int wrow0, int k0, int tid) {
    #pragma unroll
    for (int it = 0; it < 4; it++) {          // A: 128 rows x 8 x 16B
        int idx = tid + it * 256;
        int r = idx >> 3, c = idx & 7;
        CP_ASYNC16(sbuf + (uint32_t)(r * LDT + c * 8) * 2,
                   Ah + (size_t)(m0 + r) * CC + k0 + c * 8);
    }
    #pragma unroll
    for (int it = 0; it < 8; it++) {          // W: 256 rows x 8 x 16B
        int idx = tid + it * 256;
        int r = idx >> 3, c = idx & 7;
        CP_ASYNC16(sbuf + A_ARR + (uint32_t)(r * LDT + c * 8) * 2,
                   Wh + (size_t)(wrow0 + r) * CC + k0 + c * 8);
    }
}

__device__ __forceinline__ void gemm_chunk_compute(
    uint32_t sbuf, int arow, int acol, int brow, int bk, float acc[4][8][4]) {
    uint32_t sA = sbuf;
    uint32_t sW = sbuf + A_ARR;
    #pragma unroll
    for (int ks = 0; ks < QKC; ks += 16) {
        uint32_t af[4][4], bb[4][4];
        #pragma unroll
        for (int mt = 0; mt < 4; mt++)
            ldsm_x4(af[mt], sA + ((arow + mt * 16) * LDT + ks + acol) * 2);
        #pragma unroll
        for (int p = 0; p < 4; p++)
            ldsm_x4(bb[p], sW + ((brow + p * 16) * LDT + ks + bk) * 2);
        #pragma unroll
        for (int mt = 0; mt < 4; mt++)
            #pragma unroll
            for (int nt = 0; nt < 8; nt++)
                mma16816(acc[mt][nt], af[mt], &bb[nt >> 1][(nt & 1) * 2], acc[mt][nt]);
    }
}

template <int MODE>
__global__ __launch_bounds__(256, 1) void gemm_pipe_kernel(
    const __half* __restrict__ Ah, const __half* __restrict__ Whb,
    const float* __restrict__ addend,
    float* __restrict__ outq, float* __restrict__ outk,
    __half* __restrict__ vh) {
    extern __shared__ __align__(16) char sdyn[];
    uint32_t sbase = smem_u32(sdyn);

    int tid = threadIdx.x;
    int l = tid & 31, wid = tid >> 5;
    int warp_m = wid >> 2;        // 0..1 (64 rows each)
    int warp_n = wid & 3;         // 0..3 (64 cols each)
    int m0 = blockIdx.y * QM;
    int n0 = blockIdx.x * QN;

    int which = (MODE == 0) ? (n0 >> 11) : 3;
    const __half* Wh = Whb + (size_t)which * CC * CC;
    int wrow0 = (MODE == 0) ? (n0 & 2047) : n0;

    float acc[4][8][4];
    #pragma unroll
    for (int i = 0; i < 4; i++)
        #pragma unroll
        for (int j = 0; j < 8; j++)
            #pragma unroll
            for (int q = 0; q < 4; q++) acc[i][j][q] = 0.f;

    int arow = warp_m * 64 + (l & 15);
    int acol = (l >> 4) << 3;
    int brow = warp_n * 64 + (l & 7) + ((l >> 4) << 3);
    int bk   = ((l >> 3) & 1) << 3;

    const int NC = CC / QKC;  // 32
    gemm_chunk_load(sbase + 0 * BUF_B, Ah, Wh, m0, wrow0, 0, tid);
    CP_COMMIT();
    gemm_chunk_load(sbase + 1 * BUF_B, Ah, Wh, m0, wrow0, QKC, tid);
    CP_COMMIT();

    int st = 0;            // stage of chunk c
    for (int c = 0; c < NC; ++c) {
        if (c + 1 < NC) CP_WAIT1(); else CP_WAIT0();
        __syncthreads();   // stage c visible; all threads done computing c-1
        if (c + 2 < NC) {
            int st2 = st + 2; if (st2 >= 3) st2 -= 3;
            gemm_chunk_load(sbase + st2 * BUF_B, Ah, Wh, m0, wrow0,
                            (c + 2) * QKC, tid);
            CP_COMMIT();
        }
        gemm_chunk_compute(sbase + st * BUF_B, arow, acol, brow, bk, acc);
        if (++st == 3) st = 0;
    }

    // epilogue (descale by 1/WSCALE)
    #pragma unroll
    for (int mt = 0; mt < 4; mt++) {
        #pragma unroll
        for (int nt = 0; nt < 8; nt++) {
            int row = m0 + warp_m * 64 + mt * 16 + (l >> 2);
            int col = wrow0 + warp_n * 64 + nt * 8 + (l & 3) * 2;
            size_t i0 = (size_t)row * CC + col;
            size_t i1 = (size_t)(row + 8) * CC + col;
            float2 v0 = make_float2(acc[mt][nt][0] * WSCALE_INV,
                                    acc[mt][nt][1] * WSCALE_INV);
            float2 v1 = make_float2(acc[mt][nt][2] * WSCALE_INV,
                                    acc[mt][nt][3] * WSCALE_INV);
            if (MODE == 1) {
                float2 a0 = *reinterpret_cast<const float2*>(addend + i0);
                float2 a1 = *reinterpret_cast<const float2*>(addend + i1);
                v0.x += a0.x; v0.y += a0.y;
                v1.x += a1.x; v1.y += a1.y;
                *reinterpret_cast<float2*>(outq + i0) = v0;
                *reinterpret_cast<float2*>(outq + i1) = v1;
            } else if (which == 0) {
                *reinterpret_cast<float2*>(outq + i0) = v0;
                *reinterpret_cast<float2*>(outq + i1) = v1;
            } else if (which == 1) {
                *reinterpret_cast<float2*>(outk + i0) = v0;
                *reinterpret_cast<float2*>(outk + i1) = v1;
            } else {
                *reinterpret_cast<uint32_t*>(vh + i0) = packh(v0.x, v0.y);
                *reinterpret_cast<uint32_t*>(vh + i1) = packh(v1.x, v1.y);
            }
        }
    }
}

// ---------------- kernel 4: per-head rmsnorm + RoPE -> fp16 -----------------
// q pre-scaled by 1/sqrt(DH)
__global__ __launch_bounds__(256) void qknorm_rope_kernel(
    const float* __restrict__ q, const float* __restrict__ k,
    __half* __restrict__ qh, __half* __restrict__ kh) {
    int gwarp = (blockIdx.x * 256 + threadIdx.x) >> 5;
    int lane  = threadIdx.x & 31;
    int m = gwarp >> 4;
    int h = gwarp & 15;
    int t = m & (TT - 1);
    size_t base = (size_t)m * CC + h * DH;
    const float qscale = 0.08838834764831845f;  // 1/sqrt(128)

    float c0 = g_cos[t * 64 + lane],      s0 = g_sin[t * 64 + lane];
    float c1 = g_cos[t * 64 + 32 + lane], s1 = g_sin[t * 64 + 32 + lane];

    #pragma unroll
    for (int w = 0; w < 2; w++) {
        const float* p = (w ? k : q) + base;
        __half* oh = (w ? kh : qh) + base;
        float sc2 = w ? 1.0f : qscale;
        float v0 = p[lane], v1 = p[lane + 32], v2 = p[lane + 64], v3 = p[lane + 96];
        float ss = v0*v0 + v1*v1 + v2*v2 + v3*v3;
        #pragma unroll
        for (int o = 16; o > 0; o >>= 1) ss += __shfl_xor_sync(0xffffffffu, ss, o);
        float sc = rsqrtf(ss * (1.0f / 128.0f) + RMS_EPS) * sc2;
        v0 *= sc; v1 *= sc; v2 *= sc; v3 *= sc;
        oh[lane]      = __float2half_rn(v0 * c0 + v2 * s0);
        oh[lane + 64] = __float2half_rn(v2 * c0 - v0 * s0);
        oh[lane + 32] = __float2half_rn(v1 * c1 + v3 * s1);
        oh[lane + 96] = __float2half_rn(v3 * c1 - v1 * s1);
    }
}

// ---------------- kernel 5: HMMA causal flash attention (BM=128, BN=128) ----
#define AP 136   // smem pitch in halves (272B) -> conflict-free ldmatrix
// smem halves: sQ 128*AP, then 2 stages x (K 128*AP + V 128*AP)
#define ATT_SMEM ((128 + 2 * 256) * AP * 2)   // 174080 bytes

__device__ __forceinline__ void attn_load_stage(
    uint32_t st_u, const __half* __restrict__ Kh, const __half* __restrict__ Vh,
    int n0, size_t base, int tid) {
    const uint32_t V_OFF = 128 * AP * 2;
    #pragma unroll
    for (int it = 0; it < 8; it++) {
        int idx = tid + it * 256;           // 0..2047
        int r = idx >> 4, c = idx & 15;
        size_t g = base + (size_t)(n0 + r) * CC + c * 8;
        uint32_t so = (uint32_t)(r * AP + c * 8) * 2;
        CP_ASYNC16(st_u + so, Kh + g);
        CP_ASYNC16(st_u + V_OFF + so, Vh + g);
    }
}

__global__ __launch_bounds__(256, 1) void attn_mma_kernel(
    const __half* __restrict__ Qh, const __half* __restrict__ Kh,
    const __half* __restrict__ Vh, __half* __restrict__ Oh) {
    extern __shared__ __half smA[];
    __half* sQ = smA;

    int tid = threadIdx.x;
    int l = tid & 31, wid = tid >> 5;
    int qt = (int)(gridDim.x - 1 - blockIdx.x);   // heavy tiles first
    int m0 = qt * 128;
    int bh = blockIdx.y;
    int b = bh >> 4, h = bh & 15;
    size_t base = (size_t)b * TT * CC + (size_t)h * DH;

    uint32_t sQ_u = smem_u32(sQ);
    uint32_t stage_u[2];
    stage_u[0] = sQ_u + 128 * AP * 2;
    stage_u[1] = stage_u[0] + 256 * AP * 2;

    // load Q: 128 rows x 128 halves
    for (int idx = tid; idx < 128 * 16; idx += 256) {
        int r = idx >> 4, c = idx & 15;
        size_t g = base + (size_t)(m0 + r) * CC + c * 8;
        *reinterpret_cast<uint4*>(&sQ[r * AP + c * 8]) =
            *reinterpret_cast<const uint4*>(&Qh[g]);
    }

    float o[16][4];
    #pragma unroll
    for (int i = 0; i < 16; i++)
        #pragma unroll
        for (int j = 0; j < 4; j++) o[i][j] = 0.f;
    float mrow[2] = {-1e30f, -1e30f};
    float lrow[2] = {0.f, 0.f};

    int aoff = ((wid * 16 + (l & 15)) * AP + ((l >> 4) << 3)) * 2;
    int brow = (l & 7) + ((l >> 4) << 3);
    int bk   = ((l >> 3) & 1) << 3;
    int vrow = l & 15;
    int vcol = (l >> 4) << 3;

    int nkv = qt + 1;
    attn_load_stage(stage_u[0], Kh, Vh, 0, base, tid);
    CP_COMMIT();

    for (int kt = 0; kt < nkv; ++kt) {
        int n0 = kt * 128;
        uint32_t st = stage_u[kt & 1];
        if (kt + 1 < nkv) {
            attn_load_stage(stage_u[(kt + 1) & 1], Kh, Vh, (kt + 1) * 128, base, tid);
            CP_COMMIT();
            CP_WAIT1();
        } else {
            CP_WAIT0();
        }
        __syncthreads();

        uint32_t sK_u = st;
        uint32_t sV_u = st + 128 * AP * 2;

        float s[16][4];
        #pragma unroll
        for (int i = 0; i < 16; i++)
            #pragma unroll
            for (int j = 0; j < 4; j++) s[i][j] = 0.f;

        // S = Q * K^T (single pass), K processed in two 64-row halves
        #pragma unroll
        for (int ks = 0; ks < 8; ++ks) {
            uint32_t aH[4], bb[4][4];
            ldsm_x4(aH, sQ_u + aoff + ks * 32);
            #pragma unroll
            for (int p = 0; p < 4; p++)
                ldsm_x4(bb[p], sK_u + ((p * 16 + brow) * AP + ks * 16 + bk) * 2);
            #pragma unroll
            for (int nt = 0; nt < 8; nt++)
                mma16816(s[nt], aH, &bb[nt >> 1][(nt & 1) * 2], s[nt]);
            #pragma unroll
            for (int p = 0; p < 4; p++)
                ldsm_x4(bb[p], sK_u + (((p + 4) * 16 + brow) * AP + ks * 16 + bk) * 2);
            #pragma unroll
            for (int nt = 0; nt < 8; nt++)
                mma16816(s[nt + 8], aH, &bb[nt >> 1][(nt & 1) * 2], s[nt + 8]);
        }

        int gr0 = m0 + wid * 16 + (l >> 2);
        int gr1 = gr0 + 8;
        if (kt == qt) {   // diagonal tile -> causal mask
            #pragma unroll
            for (int nt = 0; nt < 16; nt++) {
                int c0 = n0 + nt * 8 + (l & 3) * 2;
                if (c0     > gr0) s[nt][0] = -1e30f;
                if (c0 + 1 > gr0) s[nt][1] = -1e30f;
                if (c0     > gr1) s[nt][2] = -1e30f;
                if (c0 + 1 > gr1) s[nt][3] = -1e30f;
            }
        }
        float tm0 = -1e30f, tm1 = -1e30f;
        #pragma unroll
        for (int nt = 0; nt < 16; nt++) {
            tm0 = fmaxf(tm0, fmaxf(s[nt][0], s[nt][1]));
            tm1 = fmaxf(tm1, fmaxf(s[nt][2], s[nt][3]));
        }
        tm0 = fmaxf(tm0, __shfl_xor_sync(0xffffffffu, tm0, 1));
        tm0 = fmaxf(tm0, __shfl_xor_sync(0xffffffffu, tm0, 2));
        tm1 = fmaxf(tm1, __shfl_xor_sync(0xffffffffu, tm1, 1));
        tm1 = fmaxf(tm1, __shfl_xor_sync(0xffffffffu, tm1, 2));
        float mn0 = fmaxf(mrow[0], tm0), mn1 = fmaxf(mrow[1], tm1);
        float al0 = fexp(mrow[0] - mn0), al1 = fexp(mrow[1] - mn1);
        float ts0 = 0.f, ts1 = 0.f;
        #pragma unroll
        for (int nt = 0; nt < 16; nt++) {
            s[nt][0] = fexp(s[nt][0] - mn0); ts0 += s[nt][0];
            s[nt][1] = fexp(s[nt][1] - mn0); ts0 += s[nt][1];
            s[nt][2] = fexp(s[nt][2] - mn1); ts1 += s[nt][2];
            s[nt][3] = fexp(s[nt][3] - mn1); ts1 += s[nt][3];
        }
        ts0 += __shfl_xor_sync(0xffffffffu, ts0, 1);
        ts0 += __shfl_xor_sync(0xffffffffu, ts0, 2);
        ts1 += __shfl_xor_sync(0xffffffffu, ts1, 1);
        ts1 += __shfl_xor_sync(0xffffffffu, ts1, 2);
        lrow[0] = lrow[0] * al0 + ts0; mrow[0] = mn0;
        lrow[1] = lrow[1] * al1 + ts1; mrow[1] = mn1;
        #pragma unroll
        for (int ot = 0; ot < 16; ot++) {
            o[ot][0] *= al0; o[ot][1] *= al0;
            o[ot][2] *= al1; o[ot][3] *= al1;
        }

        // pack P from accumulators: pH[k2] covers kv rows k2*16..k2*16+15
        uint32_t pH[8][4];
        #pragma unroll
        for (int k2 = 0; k2 < 8; k2++) {
            #pragma unroll
            for (int hx = 0; hx < 2; hx++) {
                int nt = 2 * k2 + hx;
                pH[k2][hx * 2 + 0] = packh(s[nt][0], s[nt][1]);
                pH[k2][hx * 2 + 1] = packh(s[nt][2], s[nt][3]);
            }
        }

        // O += P * V (single pass over 128 kv rows)
        #pragma unroll
        for (int k2 = 0; k2 < 8; k2++) {
            uint32_t bV[8][4];
            #pragma unroll
            for (int dv = 0; dv < 8; dv++)
                ldsm_x4_t(bV[dv], sV_u + ((k2 * 16 + vrow) * AP + dv * 16 + vcol) * 2);
            #pragma unroll
            for (int ot = 0; ot < 16; ot++)
                mma16816(o[ot], pH[k2], &bV[ot >> 1][(ot & 1) * 2], o[ot]);
        }
        __syncthreads();
    }

    // epilogue: normalize, write fp16
    float inv0 = 1.f / lrow[0], inv1 = 1.f / lrow[1];
    int gr0 = m0 + wid * 16 + (l >> 2);
    #pragma unroll
    for (int ot = 0; ot < 16; ot++) {
        size_t i0 = base + (size_t)gr0 * CC + ot * 8 + (l & 3) * 2;
        size_t i1 = i0 + (size_t)8 * CC;
        *reinterpret_cast<uint32_t*>(Oh + i0) = packh(o[ot][0] * inv0, o[ot][1] * inv0);
        *reinterpret_cast<uint32_t*>(Oh + i1) = packh(o[ot][2] * inv1, o[ot][3] * inv1);
    }
}

// ---------------- launch -----------------------------------------------------
extern "C" void kernel_launch(void* const* d_in, const int* in_sizes, int n_in,
                              void* d_out, int out_size) {
    const float* residual = (const float*)d_in[0];
    const float* w[4] = {(const float*)d_in[1], (const float*)d_in[2],
                         (const float*)d_in[3], (const float*)d_in[4]};
    float* out = (float*)d_out;

    cudaFuncSetAttribute(attn_mma_kernel, cudaFuncAttributeMaxDynamicSharedMemorySize,
                         ATT_SMEM);
    cudaFuncSetAttribute(gemm_pipe_kernel<0>,
                         cudaFuncAttributeMaxDynamicSharedMemorySize, GEMM_SMEM);
    cudaFuncSetAttribute(gemm_pipe_kernel<1>,
                         cudaFuncAttributeMaxDynamicSharedMemorySize, GEMM_SMEM);

    void *pq, *pk, *pxh, *pyh, *pwh, *pqh, *pkh, *pvh;
    cudaGetSymbolAddress(&pq, g_q);
    cudaGetSymbolAddress(&pk, g_k);
    cudaGetSymbolAddress(&pxh, g_xh);
    cudaGetSymbolAddress(&pyh, g_yh);
    cudaGetSymbolAddress(&pwh, g_wh);
    cudaGetSymbolAddress(&pqh, g_qh);
    cudaGetSymbolAddress(&pkh, g_kh);
    cudaGetSymbolAddress(&pvh, g_vh);
    float* gq = (float*)pq; float* gk = (float*)pk;
    __half* xh = (__half*)pxh; __half* yh = (__half*)pyh;
    __half* wh = (__half*)pwh;
    __half* qh = (__half*)pqh; __half* kh = (__half*)pkh; __half* vh = (__half*)pvh;

    // 0. cast all weights to fp16 (pre-scaled x32) in one launch
    castw4_kernel<<<4 * 4096, 256>>>(w[0], w[1], w[2], w[3], wh);
    // 1. rmsnorm input -> fp16
    rmsnorm_in_kernel<<<BT, 256>>>(residual, xh);
    // 2. rope tables
    rope_table_kernel<<<(TT * 64 + 255) / 256, 256>>>();
    // 3. fused QKV projection: q,k fp32; v fp16
    dim3 qkvgrid(3 * CC / QN, BT / QM);
    gemm_pipe_kernel<0><<<qkvgrid, 256, GEMM_SMEM>>>(xh, wh, nullptr, gq, gk, vh);
    // 4. per-head rmsnorm + rope -> fp16 q,k
    qknorm_rope_kernel<<<(BT * HH) / 8, 256>>>(gq, gk, qh, kh);
    // 5. HMMA causal flash attention -> fp16 y
    dim3 agrid(TT / 128, BB * HH);
    attn_mma_kernel<<<agrid, 256, ATT_SMEM>>>(qh, kh, vh, yh);
    // 6. output projection + residual add
    dim3 pgrid(CC / QN, BT / QM);
    gemm_pipe_kernel<1><<<pgrid, 256, GEMM_SMEM>>>(yh, wh, residual, out, nullptr, nullptr);
}

// round 15
// speedup vs baseline: 1.0983x; 1.0983x over previous
#include <cuda_runtime.h>
#include <cuda_fp16.h>
#include <math.h>
#include <stdint.h>

// Problem constants
#define BB   4
#define TT   2048
#define CC   2048
#define HH   16
#define DH   128
#define BT   (BB * TT)          // 8192
#define ELEMS ((size_t)BT * CC) // 16777216

#define RMS_EPS 1.1920928955078125e-07f
#define WSCALE     32.0f        // weight pre-scale (keeps small weights normal in fp16)
#define WSCALE_INV 0.03125f

// ---------------- scratch (device globals; no allocation allowed) ----------
__device__ __align__(16) __half g_xh[ELEMS];
__device__ __align__(16) __half g_yh[ELEMS];
__device__ __align__(16) __half g_qh[ELEMS];   // raw q from GEMM, normed in place
__device__ __align__(16) __half g_kh[ELEMS];   // raw k from GEMM, normed in place
__device__ __align__(16) __half g_vh[ELEMS];
__device__ __align__(16) __half g_wh[4][(size_t)CC * CC];
__device__ __align__(16) float g_cos[TT * 64];
__device__ __align__(16) float g_sin[TT * 64];

// ======================= PTX helpers (portable, no 'a' features) ============
__device__ __forceinline__ uint32_t smem_u32(const void* p) {
    uint32_t a;
    asm("{ .reg .u64 t; cvta.to.shared.u64 t, %1; cvt.u32.u64 %0, t; }"
        : "=r"(a) : "l"(p));
    return a;
}

__device__ __forceinline__ void ldsm_x4(uint32_t* r, uint32_t addr) {
    asm volatile("ldmatrix.sync.aligned.m8n8.x4.shared.b16 {%0,%1,%2,%3}, [%4];"
                 : "=r"(r[0]), "=r"(r[1]), "=r"(r[2]), "=r"(r[3]) : "r"(addr));
}
__device__ __forceinline__ void ldsm_x4_t(uint32_t* r, uint32_t addr) {
    asm volatile("ldmatrix.sync.aligned.m8n8.x4.trans.shared.b16 {%0,%1,%2,%3}, [%4];"
                 : "=r"(r[0]), "=r"(r[1]), "=r"(r[2]), "=r"(r[3]) : "r"(addr));
}

// fp16 MMA, fp32 accumulate
__device__ __forceinline__ void mma16816(float* d, const uint32_t* a,
                                         const uint32_t* b, const float* c) {
    asm volatile(
        "mma.sync.aligned.m16n8k16.row.col.f32.f16.f16.f32 "
        "{%0,%1,%2,%3}, {%4,%5,%6,%7}, {%8,%9}, {%10,%11,%12,%13};\n"
        : "=f"(d[0]), "=f"(d[1]), "=f"(d[2]), "=f"(d[3])
        : "r"(a[0]), "r"(a[1]), "r"(a[2]), "r"(a[3]),
          "r"(b[0]), "r"(b[1]),
          "f"(c[0]), "f"(c[1]), "f"(c[2]), "f"(c[3]));
}

#define CP_ASYNC16(sdst, gsrc) \
    asm volatile("cp.async.cg.shared.global [%0], [%1], 16;" \
                 :: "r"(sdst), "l"(gsrc) : "memory")
#define CP_COMMIT() asm volatile("cp.async.commit_group;" ::: "memory")
#define CP_WAIT1()  asm volatile("cp.async.wait_group 1;" ::: "memory")
#define CP_WAIT0()  asm volatile("cp.async.wait_group 0;" ::: "memory")

// pack two fp32 into f16x2 (first arg -> low half)
__device__ __forceinline__ uint32_t packh(float lo, float hi) {
    uint32_t d;
    asm("cvt.rn.f16x2.f32 %0, %1, %2;" : "=r"(d) : "f"(hi), "f"(lo));
    return d;
}

// fast e^x for x <= 0 (no MUFU): 2^y with rint + deg-5 poly, rel err ~2.4e-6
__device__ __forceinline__ float fexp(float x) {
    float y = x * 1.4426950408889634f;
    y = fmaxf(y, -126.0f);
    float nf = rintf(y);
    float f = y - nf;
    float p = 1.3333558146e-3f;
    p = fmaf(p, f, 9.6181291076e-3f);
    p = fmaf(p, f, 5.5504108664e-2f);
    p = fmaf(p, f, 2.4022650696e-1f);
    p = fmaf(p, f, 6.9314718056e-1f);
    p = fmaf(p, f, 1.0f);
    return __int_as_float(__float_as_int(p) + (((int)nf) << 23));
}

// ---------------- kernel: cast all 4 weights fp32 -> fp16 (x WSCALE) --------
__global__ __launch_bounds__(256) void castw4_kernel(const float* __restrict__ w0,
                                                     const float* __restrict__ w1,
                                                     const float* __restrict__ w2,
                                                     const float* __restrict__ w3,
                                                     __half* __restrict__ hi) {
    int gb = blockIdx.x >> 12;              // 4096 blocks per weight
    const float* in = (gb == 0) ? w0 : (gb == 1) ? w1 : (gb == 2) ? w2 : w3;
    size_t i = (size_t)(blockIdx.x & 4095) * 256 + threadIdx.x;
    float4 v = reinterpret_cast<const float4*>(in)[i];
    uint2 u;
    u.x = packh(v.x * WSCALE, v.y * WSCALE);
    u.y = packh(v.z * WSCALE, v.w * WSCALE);
    *reinterpret_cast<uint2*>(hi + (size_t)gb * CC * CC + 4 * i) = u;
}

// ---------------- kernel 1: rmsnorm over C, output fp16 ---------------------
__global__ __launch_bounds__(256) void rmsnorm_in_kernel(const float* __restrict__ in,
                                                         __half* __restrict__ xh) {
    int row = blockIdx.x;
    const float4* ip = reinterpret_cast<const float4*>(in) + (size_t)row * 512;
    int t = threadIdx.x;
    float4 a = ip[t];
    float4 b = ip[t + 256];
    float ss = a.x*a.x + a.y*a.y + a.z*a.z + a.w*a.w
             + b.x*b.x + b.y*b.y + b.z*b.z + b.w*b.w;
    __shared__ float red[8];
    #pragma unroll
    for (int o = 16; o > 0; o >>= 1) ss += __shfl_xor_sync(0xffffffffu, ss, o);
    if ((t & 31) == 0) red[t >> 5] = ss;
    __syncthreads();
    if (t < 8) {
        float v = red[t];
        #pragma unroll
        for (int o = 4; o > 0; o >>= 1) v += __shfl_xor_sync(0xffu, v, o);
        if (t == 0) red[0] = v;
    }
    __syncthreads();
    float sc = rsqrtf(red[0] * (1.0f / 2048.0f) + RMS_EPS);
    size_t base = (size_t)row * CC;
    uint2 u0, u1;
    u0.x = packh(a.x * sc, a.y * sc); u0.y = packh(a.z * sc, a.w * sc);
    u1.x = packh(b.x * sc, b.y * sc); u1.y = packh(b.z * sc, b.w * sc);
    *reinterpret_cast<uint2*>(xh + base + 4 * t)         = u0;
    *reinterpret_cast<uint2*>(xh + base + 4 * (t + 256)) = u1;
}

// ---------------- kernel 2: RoPE cos/sin tables -----------------------------
__global__ void rope_table_kernel() {
    int idx = blockIdx.x * blockDim.x + threadIdx.x;
    if (idx >= TT * 64) return;
    int t = idx >> 6;
    int p = idx & 63;
    double inv = pow(10000.0, -((double)p) / 64.0);
    float ang = (float)t * (float)inv;
    g_cos[idx] = cosf(ang);
    g_sin[idx] = sinf(ang);
}

// ---------------- kernel 3: 3-stage pipelined HMMA fp16 GEMM ----------------
// C[m,n] = (1/WSCALE) * sum_k Ah[m,k]*Wh[n,k]  (+ addend)
// Block 128x128, warp tile 64x32, Kc=64, 3-stage cp.async ring, 2 CTAs/SM.
// MODE 0: fused QKV over N=6144; q,k,v all written as fp16.
// MODE 1: proj: out = acc + addend (fp32).
#define QM 128
#define QN 128
#define QKC 64
#define LDT 72                      // smem row pitch halves (144B) -> conflict-free
#define ARR_B (QM * LDT * 2)        // 18432 bytes per array
#define BUF_B (2 * ARR_B)           // 36864 bytes per stage (A + W)
#define GEMM_SMEM (3 * BUF_B)       // 110592 bytes

__device__ __forceinline__ void gemm_chunk_load(
    uint32_t sbuf, const __half* __restrict__ Ah, const __half* __restrict__ Wh,
    int m0, int wrow0, int k0, int tid) {
    #pragma unroll
    for (int it = 0; it < 4; it++) {
        int idx = tid + it * 256;           // 0..1023
        int r = idx >> 3, c = idx & 7;
        uint32_t so = (uint32_t)(r * LDT + c * 8) * 2;
        size_t ga = (size_t)(m0 + r) * CC + k0 + c * 8;
        size_t gw = (size_t)(wrow0 + r) * CC + k0 + c * 8;
        CP_ASYNC16(sbuf + 0 * ARR_B + so, Ah + ga);
        CP_ASYNC16(sbuf + 1 * ARR_B + so, Wh + gw);
    }
}

__device__ __forceinline__ void gemm_chunk_compute(
    uint32_t sbuf, int arow, int acol, int brow, int bk, float acc[4][4][4]) {
    uint32_t sAh = sbuf;
    uint32_t sWh = sbuf + 1 * ARR_B;
    #pragma unroll
    for (int ks = 0; ks < QKC; ks += 16) {
        uint32_t af[4][4], bh[2][4];
        #pragma unroll
        for (int mt = 0; mt < 4; mt++)
            ldsm_x4(af[mt], sAh + ((arow + mt * 16) * LDT + ks + acol) * 2);
        #pragma unroll
        for (int p = 0; p < 2; p++)
            ldsm_x4(bh[p], sWh + ((brow + p * 16) * LDT + ks + bk) * 2);
        #pragma unroll
        for (int mt = 0; mt < 4; mt++)
            #pragma unroll
            for (int nt = 0; nt < 4; nt++)
                mma16816(acc[mt][nt], af[mt], &bh[nt >> 1][(nt & 1) * 2], acc[mt][nt]);
    }
}

template <int MODE>
__global__ __launch_bounds__(256, 2) void gemm_pipe_kernel(
    const __half* __restrict__ Ah, const __half* __restrict__ Whb,
    const float* __restrict__ addend, float* __restrict__ fout,
    __half* __restrict__ outq, __half* __restrict__ outk,
    __half* __restrict__ vh) {
    extern __shared__ __align__(16) char sdyn[];
    uint32_t sbase = smem_u32(sdyn);

    int tid = threadIdx.x;
    int l = tid & 31, wid = tid >> 5;
    int warp_m = wid >> 2;
    int warp_n = wid & 3;
    int m0 = blockIdx.y * QM;
    int n0 = blockIdx.x * QN;

    int which = (MODE == 0) ? (n0 >> 11) : 3;
    const __half* Wh = Whb + (size_t)which * CC * CC;
    int wrow0 = (MODE == 0) ? (n0 & 2047) : n0;

    float acc[4][4][4];
    #pragma unroll
    for (int i = 0; i < 4; i++)
        #pragma unroll
        for (int j = 0; j < 4; j++)
            #pragma unroll
            for (int q = 0; q < 4; q++) acc[i][j][q] = 0.f;

    int arow = warp_m * 64 + (l & 15);
    int acol = (l >> 4) << 3;
    int brow = warp_n * 32 + (l & 7) + ((l >> 4) << 3);
    int bk   = ((l >> 3) & 1) << 3;

    const int NC = CC / QKC;  // 32
    gemm_chunk_load(sbase + 0 * BUF_B, Ah, Wh, m0, wrow0, 0, tid);
    CP_COMMIT();
    gemm_chunk_load(sbase + 1 * BUF_B, Ah, Wh, m0, wrow0, QKC, tid);
    CP_COMMIT();

    int st = 0;            // stage of chunk c
    for (int c = 0; c < NC; ++c) {
        if (c + 1 < NC) CP_WAIT1(); else CP_WAIT0();
        __syncthreads();   // stage c visible; all threads done computing c-1
        if (c + 2 < NC) {
            int st2 = st + 2; if (st2 >= 3) st2 -= 3;
            gemm_chunk_load(sbase + st2 * BUF_B, Ah, Wh, m0, wrow0,
                            (c + 2) * QKC, tid);
            CP_COMMIT();
        }
        gemm_chunk_compute(sbase + st * BUF_B, arow, acol, brow, bk, acc);
        if (++st == 3) st = 0;
    }

    // epilogue (descale by 1/WSCALE)
    #pragma unroll
    for (int mt = 0; mt < 4; mt++) {
        #pragma unroll
        for (int nt = 0; nt < 4; nt++) {
            int row = m0 + warp_m * 64 + mt * 16 + (l >> 2);
            int col = wrow0 + warp_n * 32 + nt * 8 + (l & 3) * 2;
            size_t i0 = (size_t)row * CC + col;
            size_t i1 = (size_t)(row + 8) * CC + col;
            float2 v0 = make_float2(acc[mt][nt][0] * WSCALE_INV,
                                    acc[mt][nt][1] * WSCALE_INV);
            float2 v1 = make_float2(acc[mt][nt][2] * WSCALE_INV,
                                    acc[mt][nt][3] * WSCALE_INV);
            if (MODE == 1) {
                float2 a0 = *reinterpret_cast<const float2*>(addend + i0);
                float2 a1 = *reinterpret_cast<const float2*>(addend + i1);
                v0.x += a0.x; v0.y += a0.y;
                v1.x += a1.x; v1.y += a1.y;
                *reinterpret_cast<float2*>(fout + i0) = v0;
                *reinterpret_cast<float2*>(fout + i1) = v1;
            } else {
                __half* dst = (which == 0) ? outq : (which == 1) ? outk : vh;
                *reinterpret_cast<uint32_t*>(dst + i0) = packh(v0.x, v0.y);
                *reinterpret_cast<uint32_t*>(dst + i1) = packh(v1.x, v1.y);
            }
        }
    }
}

// ---------------- kernel 4: per-head rmsnorm + RoPE, IN PLACE on fp16 -------
// q pre-scaled by 1/sqrt(DH)
__global__ __launch_bounds__(256) void qknorm_rope_kernel(
    __half* __restrict__ q, __half* __restrict__ k) {
    int gwarp = (blockIdx.x * 256 + threadIdx.x) >> 5;
    int lane  = threadIdx.x & 31;
    int m = gwarp >> 4;
    int h = gwarp & 15;
    int t = m & (TT - 1);
    size_t base = (size_t)m * CC + h * DH;
    const float qscale = 0.08838834764831845f;  // 1/sqrt(128)

    float c0 = g_cos[t * 64 + lane],      s0 = g_sin[t * 64 + lane];
    float c1 = g_cos[t * 64 + 32 + lane], s1 = g_sin[t * 64 + 32 + lane];

    #pragma unroll
    for (int w = 0; w < 2; w++) {
        __half* p = (w ? k : q) + base;
        float sc2 = w ? 1.0f : qscale;
        float v0 = __half2float(p[lane]);
        float v1 = __half2float(p[lane + 32]);
        float v2 = __half2float(p[lane + 64]);
        float v3 = __half2float(p[lane + 96]);
        float ss = v0*v0 + v1*v1 + v2*v2 + v3*v3;
        #pragma unroll
        for (int o = 16; o > 0; o >>= 1) ss += __shfl_xor_sync(0xffffffffu, ss, o);
        float sc = rsqrtf(ss * (1.0f / 128.0f) + RMS_EPS) * sc2;
        v0 *= sc; v1 *= sc; v2 *= sc; v3 *= sc;
        p[lane]      = __float2half_rn(v0 * c0 + v2 * s0);
        p[lane + 64] = __float2half_rn(v2 * c0 - v0 * s0);
        p[lane + 32] = __float2half_rn(v1 * c1 + v3 * s1);
        p[lane + 96] = __float2half_rn(v3 * c1 - v1 * s1);
    }
}

// ---------------- kernel 5: HMMA causal flash attention (BM=128, BN=128) ----
#define AP 136   // smem pitch in halves (272B) -> conflict-free ldmatrix
// smem halves: sQ 128*AP, then 2 stages x (K 128*AP + V 128*AP)
#define ATT_SMEM ((128 + 2 * 256) * AP * 2)   // 174080 bytes

__device__ __forceinline__ void attn_load_stage(
    uint32_t st_u, const __half* __restrict__ Kh, const __half* __restrict__ Vh,
    int n0, size_t base, int tid) {
    const uint32_t V_OFF = 128 * AP * 2;
    #pragma unroll
    for (int it = 0; it < 8; it++) {
        int idx = tid + it * 256;           // 0..2047
        int r = idx >> 4, c = idx & 15;
        size_t g = base + (size_t)(n0 + r) * CC + c * 8;
        uint32_t so = (uint32_t)(r * AP + c * 8) * 2;
        CP_ASYNC16(st_u + so, Kh + g);
        CP_ASYNC16(st_u + V_OFF + so, Vh + g);
    }
}

__global__ __launch_bounds__(256, 1) void attn_mma_kernel(
    const __half* __restrict__ Qh, const __half* __restrict__ Kh,
    const __half* __restrict__ Vh, __half* __restrict__ Oh) {
    extern __shared__ __half smA[];
    __half* sQ = smA;

    int tid = threadIdx.x;
    int l = tid & 31, wid = tid >> 5;
    int qt = (int)(gridDim.x - 1 - blockIdx.x);   // heavy tiles first
    int m0 = qt * 128;
    int bh = blockIdx.y;
    int b = bh >> 4, h = bh & 15;
    size_t base = (size_t)b * TT * CC + (size_t)h * DH;

    uint32_t sQ_u = smem_u32(sQ);
    uint32_t stage_u[2];
    stage_u[0] = sQ_u + 128 * AP * 2;
    stage_u[1] = stage_u[0] + 256 * AP * 2;

    // load Q: 128 rows x 128 halves
    for (int idx = tid; idx < 128 * 16; idx += 256) {
        int r = idx >> 4, c = idx & 15;
        size_t g = base + (size_t)(m0 + r) * CC + c * 8;
        *reinterpret_cast<uint4*>(&sQ[r * AP + c * 8]) =
            *reinterpret_cast<const uint4*>(&Qh[g]);
    }

    float o[16][4];
    #pragma unroll
    for (int i = 0; i < 16; i++)
        #pragma unroll
        for (int j = 0; j < 4; j++) o[i][j] = 0.f;
    float mrow[2] = {-1e30f, -1e30f};
    float lrow[2] = {0.f, 0.f};

    int aoff = ((wid * 16 + (l & 15)) * AP + ((l >> 4) << 3)) * 2;
    int brow = (l & 7) + ((l >> 4) << 3);
    int bk   = ((l >> 3) & 1) << 3;
    int vrow = l & 15;
    int vcol = (l >> 4) << 3;

    int nkv = qt + 1;
    attn_load_stage(stage_u[0], Kh, Vh, 0, base, tid);
    CP_COMMIT();

    for (int kt = 0; kt < nkv; ++kt) {
        int n0 = kt * 128;
        uint32_t st = stage_u[kt & 1];
        if (kt + 1 < nkv) {
            attn_load_stage(stage_u[(kt + 1) & 1], Kh, Vh, (kt + 1) * 128, base, tid);
            CP_COMMIT();
            CP_WAIT1();
        } else {
            CP_WAIT0();
        }
        __syncthreads();

        uint32_t sK_u = st;
        uint32_t sV_u = st + 128 * AP * 2;

        float s[16][4];
        #pragma unroll
        for (int i = 0; i < 16; i++)
            #pragma unroll
            for (int j = 0; j < 4; j++) s[i][j] = 0.f;

        // S = Q * K^T (single pass), K processed in two 64-row halves
        #pragma unroll
        for (int ks = 0; ks < 8; ++ks) {
            uint32_t aH[4], bb[4][4];
            ldsm_x4(aH, sQ_u + aoff + ks * 32);
            #pragma unroll
            for (int p = 0; p < 4; p++)
                ldsm_x4(bb[p], sK_u + ((p * 16 + brow) * AP + ks * 16 + bk) * 2);
            #pragma unroll
            for (int nt = 0; nt < 8; nt++)
                mma16816(s[nt], aH, &bb[nt >> 1][(nt & 1) * 2], s[nt]);
            #pragma unroll
            for (int p = 0; p < 4; p++)
                ldsm_x4(bb[p], sK_u + (((p + 4) * 16 + brow) * AP + ks * 16 + bk) * 2);
            #pragma unroll
            for (int nt = 0; nt < 8; nt++)
                mma16816(s[nt + 8], aH, &bb[nt >> 1][(nt & 1) * 2], s[nt + 8]);
        }

        int gr0 = m0 + wid * 16 + (l >> 2);
        int gr1 = gr0 + 8;
        if (kt == qt) {   // diagonal tile -> causal mask
            #pragma unroll
            for (int nt = 0; nt < 16; nt++) {
                int c0 = n0 + nt * 8 + (l & 3) * 2;
                if (c0     > gr0) s[nt][0] = -1e30f;
                if (c0 + 1 > gr0) s[nt][1] = -1e30f;
                if (c0     > gr1) s[nt][2] = -1e30f;
                if (c0 + 1 > gr1) s[nt][3] = -1e30f;
            }
        }
        float tm0 = -1e30f, tm1 = -1e30f;
        #pragma unroll
        for (int nt = 0; nt < 16; nt++) {
            tm0 = fmaxf(tm0, fmaxf(s[nt][0], s[nt][1]));
            tm1 = fmaxf(tm1, fmaxf(s[nt][2], s[nt][3]));
        }
        tm0 = fmaxf(tm0, __shfl_xor_sync(0xffffffffu, tm0, 1));
        tm0 = fmaxf(tm0, __shfl_xor_sync(0xffffffffu, tm0, 2));
        tm1 = fmaxf(tm1, __shfl_xor_sync(0xffffffffu, tm1, 1));
        tm1 = fmaxf(tm1, __shfl_xor_sync(0xffffffffu, tm1, 2));
        float mn0 = fmaxf(mrow[0], tm0), mn1 = fmaxf(mrow[1], tm1);
        float al0 = fexp(mrow[0] - mn0), al1 = fexp(mrow[1] - mn1);
        float ts0 = 0.f, ts1 = 0.f;
        #pragma unroll
        for (int nt = 0; nt < 16; nt++) {
            s[nt][0] = fexp(s[nt][0] - mn0); ts0 += s[nt][0];
            s[nt][1] = fexp(s[nt][1] - mn0); ts0 += s[nt][1];
            s[nt][2] = fexp(s[nt][2] - mn1); ts1 += s[nt][2];
            s[nt][3] = fexp(s[nt][3] - mn1); ts1 += s[nt][3];
        }
        ts0 += __shfl_xor_sync(0xffffffffu, ts0, 1);
        ts0 += __shfl_xor_sync(0xffffffffu, ts0, 2);
        ts1 += __shfl_xor_sync(0xffffffffu, ts1, 1);
        ts1 += __shfl_xor_sync(0xffffffffu, ts1, 2);
        lrow[0] = lrow[0] * al0 + ts0; mrow[0] = mn0;
        lrow[1] = lrow[1] * al1 + ts1; mrow[1] = mn1;
        #pragma unroll
        for (int ot = 0; ot < 16; ot++) {
            o[ot][0] *= al0; o[ot][1] *= al0;
            o[ot][2] *= al1; o[ot][3] *= al1;
        }

        // pack P from accumulators: pH[k2] covers kv rows k2*16..k2*16+15
        uint32_t pH[8][4];
        #pragma unroll
        for (int k2 = 0; k2 < 8; k2++) {
            #pragma unroll
            for (int hx = 0; hx < 2; hx++) {
                int nt = 2 * k2 + hx;
                pH[k2][hx * 2 + 0] = packh(s[nt][0], s[nt][1]);
                pH[k2][hx * 2 + 1] = packh(s[nt][2], s[nt][3]);
            }
        }

        // O += P * V (single pass over 128 kv rows)
        #pragma unroll
        for (int k2 = 0; k2 < 8; k2++) {
            uint32_t bV[8][4];
            #pragma unroll
            for (int dv = 0; dv < 8; dv++)
                ldsm_x4_t(bV[dv], sV_u + ((k2 * 16 + vrow) * AP + dv * 16 + vcol) * 2);
            #pragma unroll
            for (int ot = 0; ot < 16; ot++)
                mma16816(o[ot], pH[k2], &bV[ot >> 1][(ot & 1) * 2], o[ot]);
        }
        __syncthreads();
    }

    // epilogue: normalize, write fp16
    float inv0 = 1.f / lrow[0], inv1 = 1.f / lrow[1];
    int gr0 = m0 + wid * 16 + (l >> 2);
    #pragma unroll
    for (int ot = 0; ot < 16; ot++) {
        size_t i0 = base + (size_t)gr0 * CC + ot * 8 + (l & 3) * 2;
        size_t i1 = i0 + (size_t)8 * CC;
        *reinterpret_cast<uint32_t*>(Oh + i0) = packh(o[ot][0] * inv0, o[ot][1] * inv0);
        *reinterpret_cast<uint32_t*>(Oh + i1) = packh(o[ot][2] * inv1, o[ot][3] * inv1);
    }
}

// ---------------- launch -----------------------------------------------------
extern "C" void kernel_launch(void* const* d_in, const int* in_sizes, int n_in,
                              void* d_out, int out_size) {
    const float* residual = (const float*)d_in[0];
    const float* w[4] = {(const float*)d_in[1], (const float*)d_in[2],
                         (const float*)d_in[3], (const float*)d_in[4]};
    float* out = (float*)d_out;

    cudaFuncSetAttribute(attn_mma_kernel, cudaFuncAttributeMaxDynamicSharedMemorySize,
                         ATT_SMEM);
    cudaFuncSetAttribute(gemm_pipe_kernel<0>,
                         cudaFuncAttributeMaxDynamicSharedMemorySize, GEMM_SMEM);
    cudaFuncSetAttribute(gemm_pipe_kernel<1>,
                         cudaFuncAttributeMaxDynamicSharedMemorySize, GEMM_SMEM);

    void *pxh, *pyh, *pwh, *pqh, *pkh, *pvh;
    cudaGetSymbolAddress(&pxh, g_xh);
    cudaGetSymbolAddress(&pyh, g_yh);
    cudaGetSymbolAddress(&pwh, g_wh);
    cudaGetSymbolAddress(&pqh, g_qh);
    cudaGetSymbolAddress(&pkh, g_kh);
    cudaGetSymbolAddress(&pvh, g_vh);
    __half* xh = (__half*)pxh; __half* yh = (__half*)pyh;
    __half* wh = (__half*)pwh;
    __half* qh = (__half*)pqh; __half* kh = (__half*)pkh; __half* vh = (__half*)pvh;

    // 0. cast all weights to fp16 (pre-scaled x32) in one launch
    castw4_kernel<<<4 * 4096, 256>>>(w[0], w[1], w[2], w[3], wh);
    // 1. rmsnorm input -> fp16
    rmsnorm_in_kernel<<<BT, 256>>>(residual, xh);
    // 2. rope tables
    rope_table_kernel<<<(TT * 64 + 255) / 256, 256>>>();
    // 3. fused QKV projection: q,k,v all fp16
    dim3 qkvgrid(3 * CC / QN, BT / QM);
    gemm_pipe_kernel<0><<<qkvgrid, 256, GEMM_SMEM>>>(
        xh, wh, nullptr, nullptr, qh, kh, vh);
    // 4. per-head rmsnorm + rope, in place on fp16 q,k
    qknorm_rope_kernel<<<(BT * HH) / 8, 256>>>(qh, kh);
    // 5. HMMA causal flash attention -> fp16 y
    dim3 agrid(TT / 128, BB * HH);
    attn_mma_kernel<<<agrid, 256, ATT_SMEM>>>(qh, kh, vh, yh);
    // 6. output projection + residual add
    dim3 pgrid(CC / QN, BT / QM);
    gemm_pipe_kernel<1><<<pgrid, 256, GEMM_SMEM>>>(
        yh, wh, residual, out, nullptr, nullptr, nullptr);
}